// round 2
// baseline (speedup 1.0000x reference)
#include <cuda_runtime.h>
#include <math_constants.h>

// StratifiedMaxPooling: out[b,c] = max_{j: labels[j]==c} values[b,j]
// values: [B=128, N=200000] f32, labels: [N] int32 (JAX x64-disabled!), C=100.
//
// Strategy: stream values once (HBM-bound). Shared accumulator of ordered-int
// keys acc[B][C]; rows partitioned across warps (no cross-warp races).
// Intra-warp same-class conflicts resolved with match_any + redux.max.s32 +
// leader-only shared RMW. Match structure is row-invariant -> computed once
// per 128-column group, reused across 4 rows. Per-block partials flushed to
// global scratch; tiny second kernel reduces partials and un-keys to float.

#define FULLMASK 0xFFFFFFFFu

static const int GRID_MAIN   = 148;    // one block per SM
static const int THREADS_MAIN = 1024;  // 32 warps
static const int B_CONST = 128;
static const int C_CONST = 100;
static const int NACC = B_CONST * C_CONST;        // 12800
static const int SMEM_INTS = NACC + 32;           // + per-lane dump slots

#define KEY_NEG_INF ((int)0x807FFFFF)  // key(-inf)

// 7.6 MB static scratch: one partial accumulator per block
__device__ int g_scratch[GRID_MAIN * NACC];

// Monotonic float->int key (no NaNs in input). Involution for decode.
__device__ __forceinline__ int fkey(float f) {
    int x = __float_as_int(f);
    return x ^ ((x >> 31) & 0x7fffffff);
}

__global__ __launch_bounds__(THREADS_MAIN, 1)
void pool_kernel(const float* __restrict__ values,
                 const int* __restrict__ labels,
                 int N, int ngroups)
{
    extern __shared__ int sacc[];  // [NACC + 32]
    const int tid  = threadIdx.x;
    const int lane = tid & 31;
    const int warp = tid >> 5;

    for (int i = tid; i < SMEM_INTS; i += THREADS_MAIN) sacc[i] = KEY_NEG_INF;
    __syncthreads();

    const unsigned lt_mask = (1u << lane) - 1u;
    // Warp w owns rows {w, w+32, w+64, w+96}
    int rowbase[4];
#pragma unroll
    for (int r = 0; r < 4; r++) rowbase[r] = (warp + (r << 5)) * C_CONST;

    const int dump = NACC + lane;  // per-lane dump slot (bank == lane)

    for (int g = blockIdx.x; g < ngroups; g += gridDim.x) {
        const int j = (g << 7) + (lane << 2);   // 4 columns per lane
        const bool ok = (j + 3) < N;            // N % 4 == 0 -> int4/float4-safe

        int c0 = 0, c1 = 0, c2 = 0, c3 = 0;
        if (ok) {
            int4 lv = *reinterpret_cast<const int4*>(labels + j);
            c0 = lv.x; c1 = lv.y; c2 = lv.z; c3 = lv.w;
        }

        // Row-invariant conflict structure for this group
        const unsigned m0 = __match_any_sync(FULLMASK, c0);
        const unsigned m1 = __match_any_sync(FULLMASK, c1);
        const unsigned m2 = __match_any_sync(FULLMASK, c2);
        const unsigned m3 = __match_any_sync(FULLMASK, c3);
        const bool ld0 = (m0 & lt_mask) == 0u;
        const bool ld1 = (m1 & lt_mask) == 0u;
        const bool ld2 = (m2 & lt_mask) == 0u;
        const bool ld3 = (m3 & lt_mask) == 0u;

#pragma unroll
        for (int r = 0; r < 4; r++) {
            const int row = warp + (r << 5);
            float4 v;
            if (ok) {
                v = *reinterpret_cast<const float4*>(values + (size_t)row * N + j);
            } else {
                v = make_float4(-CUDART_INF_F, -CUDART_INF_F,
                                -CUDART_INF_F, -CUDART_INF_F);
            }
            int k0 = __reduce_max_sync(m0, fkey(v.x));
            int k1 = __reduce_max_sync(m1, fkey(v.y));
            int k2 = __reduce_max_sync(m2, fkey(v.z));
            int k3 = __reduce_max_sync(m3, fkey(v.w));

            // Leader-only RMW; non-leaders hit their private dump slot so the
            // store is unconditional (no BSSY/BSYNC around a guarded arm).
            const int rb = rowbase[r];
            int a0 = ld0 ? rb + c0 : dump;
            int a1 = ld1 ? rb + c1 : dump;
            int a2 = ld2 ? rb + c2 : dump;
            int a3 = ld3 ? rb + c3 : dump;
            sacc[a0] = max(sacc[a0], k0);
            sacc[a1] = max(sacc[a1], k1);
            sacc[a2] = max(sacc[a2], k2);
            sacc[a3] = max(sacc[a3], k3);
        }
    }

    __syncthreads();
    int* dst = g_scratch + (size_t)blockIdx.x * NACC;
    for (int i = tid; i < NACC; i += THREADS_MAIN) dst[i] = sacc[i];
}

__global__ void reduce_kernel(float* __restrict__ out, int nparts)
{
    const int i = blockIdx.x * blockDim.x + threadIdx.x;
    if (i >= NACC) return;
    int best = KEY_NEG_INF;
#pragma unroll 4
    for (int t = 0; t < nparts; t++)
        best = max(best, g_scratch[(size_t)t * NACC + i]);
    // inverse key
    if (best < 0) best ^= 0x7fffffff;
    out[i] = __int_as_float(best);
}

extern "C" void kernel_launch(void* const* d_in, const int* in_sizes, int n_in,
                              void* d_out, int out_size)
{
    const float* values = (const float*)d_in[0];
    const int*   labels = (const int*)d_in[1];
    const int N = in_sizes[1];            // 200000
    const int ngroups = (N + 127) >> 7;   // 1563

    const int smem_bytes = SMEM_INTS * (int)sizeof(int);  // 51328 B > 48K
    cudaFuncSetAttribute(pool_kernel,
                         cudaFuncAttributeMaxDynamicSharedMemorySize,
                         smem_bytes);

    pool_kernel<<<GRID_MAIN, THREADS_MAIN, smem_bytes>>>(values, labels, N, ngroups);

    const int rthreads = 256;
    const int rblocks = (NACC + rthreads - 1) / rthreads;
    reduce_kernel<<<rblocks, rthreads>>>((float*)d_out, GRID_MAIN);
}

// round 3
// speedup vs baseline: 4.2898x; 4.2898x over previous
#include <cuda_runtime.h>
#include <math_constants.h>

// StratifiedMaxPooling: out[b,c] = max_{j: labels[j]==c} values[b,j]
// values: [B=128, N=200000] f32, labels: [N] int32, C=100.
//
// R3 design: stream values once (HBM-bound). Shared accumulator of ordered-int
// keys acc[B][C]; rows partitioned across warps. Intra-warp same-class
// conflicts resolved with a rank/round scheme (NO partition-masked REDUX —
// those replay per distinct mask subgroup, ~27x here). Conflict structure is
// row-invariant -> computed once per 128-column group, reused across 4 rows.
// Cross-block combine: global atomicMax (REDG.MAX) instead of scratch+reduce.

#define FULLMASK 0xFFFFFFFFu

static const int GRID_MAIN    = 148;   // one block per SM
static const int THREADS_MAIN = 1024;  // 32 warps
static const int C_CONST = 100;
static const int NACC = 128 * C_CONST;      // 12800
static const int SMEM_INTS = NACC + 32;     // + per-lane dump slots

#define KEY_NEG_INF ((int)0x807FFFFF)  // key(-inf)

__device__ int g_keys[NACC];  // cross-block accumulator (int keys)

// Monotonic float->int key (no NaNs in input). Involution for decode.
__device__ __forceinline__ int fkey(float f) {
    int x = __float_as_int(f);
    return x ^ ((x >> 31) & 0x7fffffff);
}

__global__ void init_kernel() {
    int i = blockIdx.x * blockDim.x + threadIdx.x;
    if (i < NACC) g_keys[i] = KEY_NEG_INF;
}

__global__ __launch_bounds__(THREADS_MAIN, 1)
void pool_kernel(const float* __restrict__ values,
                 const int* __restrict__ labels,
                 int N, int ngroups)
{
    extern __shared__ int sacc_[];         // [NACC + 32]
    volatile int* sacc = sacc_;            // keep round-to-round RMWs honest
    const int tid  = threadIdx.x;
    const int lane = tid & 31;
    const int warp = tid >> 5;

    for (int i = tid; i < SMEM_INTS; i += THREADS_MAIN) sacc_[i] = KEY_NEG_INF;
    __syncthreads();

    const unsigned lt_mask = (1u << lane) - 1u;
    // Warp w owns rows {w, w+32, w+64, w+96}
    int rowbase[4];
#pragma unroll
    for (int r = 0; r < 4; r++) rowbase[r] = (warp + (r << 5)) * C_CONST;

    const int dump = NACC + lane;  // per-lane dump slot (bank == lane)

    for (int g = blockIdx.x; g < ngroups; g += gridDim.x) {
        const int j = (g << 7) + (lane << 2);   // 4 columns per lane
        const bool ok = (j + 3) < N;            // all-or-nothing per lane

        int c0 = 0, c1 = 0, c2 = 0, c3 = 0;
        if (ok) {
            int4 lv = *reinterpret_cast<const int4*>(labels + j);
            c0 = lv.x; c1 = lv.y; c2 = lv.z; c3 = lv.w;
        }

        // Row-invariant conflict structure (computed once, reused for 4 rows)
        const unsigned m0 = __match_any_sync(FULLMASK, c0);
        const unsigned m1 = __match_any_sync(FULLMASK, c1);
        const unsigned m2 = __match_any_sync(FULLMASK, c2);
        const unsigned m3 = __match_any_sync(FULLMASK, c3);
        const int r0 = __popc(m0 & lt_mask);   // my round for slot 0
        const int r1 = __popc(m1 & lt_mask);
        const int r2 = __popc(m2 & lt_mask);
        const int r3 = __popc(m3 & lt_mask);
        int mult = max(max(__popc(m0), __popc(m1)),
                       max(__popc(m2), __popc(m3)));
        // Uniform-mask redux: single instruction, no subgroup replay.
        const int M = __reduce_max_sync(FULLMASK, mult);

        // Load 4 rows x 4 cols, convert to keys
        int kv[4][4];
#pragma unroll
        for (int r = 0; r < 4; r++) {
            const int row = warp + (r << 5);
            float4 v;
            if (ok) {
                v = __ldcs(reinterpret_cast<const float4*>(
                        values + (size_t)row * N + j));
            } else {
                v = make_float4(-CUDART_INF_F, -CUDART_INF_F,
                                -CUDART_INF_F, -CUDART_INF_F);
            }
            kv[r][0] = fkey(v.x); kv[r][1] = fkey(v.y);
            kv[r][2] = fkey(v.z); kv[r][3] = fkey(v.w);
        }

        // Round-robin RMW: at round t, only rank==t lanes touch their class
        // slot (distinct addresses within a slot); others hit a private dump
        // slot so every store is unconditional (no BSSY/BSYNC).
        for (int round = 0; round < M; round++) {
            const int t0 = (r0 == round) ? c0 : (dump - rowbase[0]);
            const int t1 = (r1 == round) ? c1 : (dump - rowbase[0]);
            const int t2 = (r2 == round) ? c2 : (dump - rowbase[0]);
            const int t3 = (r3 == round) ? c3 : (dump - rowbase[0]);
#pragma unroll
            for (int r = 0; r < 4; r++) {
                const int d = rowbase[r] - rowbase[0];
                int a0 = rowbase[0] + t0 + ((r0 == round) ? d : 0);
                int a1 = rowbase[0] + t1 + ((r1 == round) ? d : 0);
                int a2 = rowbase[0] + t2 + ((r2 == round) ? d : 0);
                int a3 = rowbase[0] + t3 + ((r3 == round) ? d : 0);
                sacc[a0] = max(sacc[a0], kv[r][0]);
                sacc[a1] = max(sacc[a1], kv[r][1]);
                sacc[a2] = max(sacc[a2], kv[r][2]);
                sacc[a3] = max(sacc[a3], kv[r][3]);
            }
            __syncwarp();
        }
    }

    __syncthreads();
    // Cross-block combine: spread REDG.MAX over 12800 addresses.
    for (int i = tid; i < NACC; i += THREADS_MAIN)
        atomicMax(&g_keys[i], sacc_[i]);
}

__global__ void finalize_kernel(float* __restrict__ out) {
    int i = blockIdx.x * blockDim.x + threadIdx.x;
    if (i >= NACC) return;
    int best = g_keys[i];
    if (best < 0) best ^= 0x7fffffff;   // inverse key
    out[i] = __int_as_float(best);
}

extern "C" void kernel_launch(void* const* d_in, const int* in_sizes, int n_in,
                              void* d_out, int out_size)
{
    const float* values = (const float*)d_in[0];
    const int*   labels = (const int*)d_in[1];
    const int N = in_sizes[1];            // 200000
    const int ngroups = (N + 127) >> 7;   // 1563

    const int smem_bytes = SMEM_INTS * (int)sizeof(int);  // 51328 B
    cudaFuncSetAttribute(pool_kernel,
                         cudaFuncAttributeMaxDynamicSharedMemorySize,
                         smem_bytes);

    init_kernel<<<(NACC + 1023) / 1024, 1024>>>();
    pool_kernel<<<GRID_MAIN, THREADS_MAIN, smem_bytes>>>(values, labels, N, ngroups);
    finalize_kernel<<<(NACC + 1023) / 1024, 1024>>>((float*)d_out);
}